// round 1
// baseline (speedup 1.0000x reference)
#include <cuda_runtime.h>
#include <cstdint>

#define D_  2048
#define H_  1408
#define HS_ 2816
#define E_  8
#define N_  4096
#define NK_ (2*N_)

typedef unsigned long long ull;

// Scratch (no allocation allowed anywhere): 46.1 MB activation buffer reused
// by shared (4096x2816) and routed (8192x1408) paths — both exactly 11,534,336.
__device__ float g_hbuf[11534336];
__device__ int   g_perm[NK_];
__device__ float g_pgate[NK_];
__device__ int   g_counts[E_];
__device__ int   g_offsets[E_ + 1];
__device__ int   g_gidx[NK_];
__device__ float g_gval[NK_];

__device__ __forceinline__ void ffma2(ull &c, ull a, ull b) {
    asm("fma.rn.f32x2 %0, %1, %2, %0;" : "+l"(c) : "l"(a), "l"(b));
}
__device__ __forceinline__ ull pack2(float x, float y) {
    ull r;
    asm("mov.b64 %0, {%1, %2};" : "=l"(r) : "r"(__float_as_uint(x)), "r"(__float_as_uint(y)));
    return r;
}
__device__ __forceinline__ float2 unpack2(ull v) {
    unsigned lo, hi;
    asm("mov.b64 {%0, %1}, %2;" : "=r"(lo), "=r"(hi) : "l"(v));
    return make_float2(__uint_as_float(lo), __uint_as_float(hi));
}

// ---------------------------------------------------------------------------
// Router: one warp per token. logits = x_row @ router_w^T, softmax, top-2,
// normalized gates (matches reference incl. EPS).
// ---------------------------------------------------------------------------
__global__ void router_kernel(const float* __restrict__ x, const float* __restrict__ rw) {
    int gw = (blockIdx.x * blockDim.x + threadIdx.x) >> 5;
    int lane = threadIdx.x & 31;
    if (gw >= N_) return;
    const float* xr = x + (size_t)gw * D_;
    float acc[E_];
#pragma unroll
    for (int e = 0; e < E_; e++) acc[e] = 0.f;
    for (int d = lane * 4; d < D_; d += 128) {
        float4 xv = *(const float4*)(xr + d);
#pragma unroll
        for (int e = 0; e < E_; e++) {
            float4 wv = *(const float4*)(rw + e * D_ + d);
            acc[e] += xv.x * wv.x + xv.y * wv.y + xv.z * wv.z + xv.w * wv.w;
        }
    }
#pragma unroll
    for (int e = 0; e < E_; e++) {
#pragma unroll
        for (int o = 16; o > 0; o >>= 1)
            acc[e] += __shfl_down_sync(0xffffffffu, acc[e], o);
    }
    if (lane == 0) {
        float mx = acc[0];
#pragma unroll
        for (int e = 1; e < E_; e++) mx = fmaxf(mx, acc[e]);
        float p[E_], s = 0.f;
#pragma unroll
        for (int e = 0; e < E_; e++) { p[e] = expf(acc[e] - mx); s += p[e]; }
        int i1 = 0;
#pragma unroll
        for (int e = 1; e < E_; e++) if (p[e] > p[i1]) i1 = e;
        int i2 = (i1 == 0) ? 1 : 0;
#pragma unroll
        for (int e = 0; e < E_; e++) if (e != i1 && p[e] > p[i2]) i2 = e;
        float g1 = p[i1] / s, g2 = p[i2] / s;
        float den = g1 + g2 + 1e-20f;
        g_gidx[2 * gw]     = i1; g_gval[2 * gw]     = g1 / den;
        g_gidx[2 * gw + 1] = i2; g_gval[2 * gw + 1] = g2 / den;
    }
}

// ---------------------------------------------------------------------------
// Build per-expert token lists deterministically (token-ascending order).
// One block; warp e handles expert e via ballot prefix scans.
// ---------------------------------------------------------------------------
__global__ void build_lists_kernel() {
    __shared__ int scnt[E_];
    __shared__ int soff[E_];
    int wid = threadIdx.x >> 5, lane = threadIdx.x & 31;
    if (wid < E_) {
        int c = 0;
        for (int base = 0; base < NK_; base += 32) {
            int flag = (g_gidx[base + lane] == wid);
            c += __popc(__ballot_sync(0xffffffffu, flag));
        }
        if (lane == 0) scnt[wid] = c;
    }
    __syncthreads();
    if (threadIdx.x == 0) {
        int s = 0;
        for (int e = 0; e < E_; e++) {
            soff[e] = s; g_offsets[e] = s; g_counts[e] = scnt[e]; s += scnt[e];
        }
        g_offsets[E_] = s;
    }
    __syncthreads();
    if (wid < E_) {
        int pos = soff[wid];
        for (int base = 0; base < NK_; base += 32) {
            int t = base + lane;
            int flag = (g_gidx[t] == wid);
            unsigned m = __ballot_sync(0xffffffffu, flag);
            if (flag) {
                int off = __popc(m & ((1u << lane) - 1u));
                g_perm[pos + off]  = t >> 1;
                g_pgate[pos + off] = g_gval[t];
            }
            pos += __popc(m);
        }
    }
}

// ---------------------------------------------------------------------------
// Fused gate/up GEMM + SiLU epilogue -> g_hbuf.
// BM=128 BN=64 BK=16, 256 threads, 8x4 per-thread tile, f32x2 packed FMA.
// ROUTED: rows gathered through g_perm per expert; else identity over N_.
// ---------------------------------------------------------------------------
template<bool ROUTED>
__global__ void __launch_bounds__(256, 2)
gateup_kernel(const float* __restrict__ x,
              const float* __restrict__ Wg,
              const float* __restrict__ Wu,
              int Nn)  // H_ (routed) or HS_ (shared) — B row stride & hbuf stride
{
    int e    = ROUTED ? blockIdx.z   : 0;
    int M    = ROUTED ? g_counts[e]  : N_;
    int base = ROUTED ? g_offsets[e] : 0;
    int m0 = blockIdx.x * 128;
    if (m0 >= M) return;
    int n0 = blockIdx.y * 64;
    const float* B1 = Wg + (ROUTED ? (size_t)e * D_ * H_ : 0);
    const float* B2 = Wu + (ROUTED ? (size_t)e * D_ * H_ : 0);

    __shared__ float sA[16][128];
    __shared__ float sB1[16][64];
    __shared__ float sB2[16][64];

    int tid = threadIdx.x;
    // A loader: thread -> row ra, 8 consecutive k at ka
    int ra = tid >> 1;
    int ka = (tid & 1) * 8;
    int gm = m0 + ra;
    bool aok = gm < M;
    int token = 0;
    if (aok) token = ROUTED ? g_perm[base + gm] : gm;
    const float* aptr = x + (size_t)token * D_ + ka;

    // B loader: thread -> k row kb, 4 cols at nb
    int kb = tid >> 4;
    int nb = (tid & 15) * 4;
    const float* b1ptr = B1 + (size_t)kb * Nn + n0 + nb;
    const float* b2ptr = B2 + (size_t)kb * Nn + n0 + nb;
    size_t bstep = (size_t)16 * Nn;

    int ty = tid >> 4;   // 16 x 8 rows
    int tx = tid & 15;   // 16 x 4 cols

    ull c1[8][2], c2[8][2];
#pragma unroll
    for (int i = 0; i < 8; i++) { c1[i][0] = c1[i][1] = c2[i][0] = c2[i][1] = 0ull; }

    float4 la0, la1, lb1, lb2;
    la0 = aok ? *(const float4*)(aptr)     : make_float4(0, 0, 0, 0);
    la1 = aok ? *(const float4*)(aptr + 4) : make_float4(0, 0, 0, 0);
    lb1 = *(const float4*)b1ptr;
    lb2 = *(const float4*)b2ptr;

    for (int kt = 0; kt < D_; kt += 16) {
        __syncthreads();
        sA[ka + 0][ra] = la0.x; sA[ka + 1][ra] = la0.y;
        sA[ka + 2][ra] = la0.z; sA[ka + 3][ra] = la0.w;
        sA[ka + 4][ra] = la1.x; sA[ka + 5][ra] = la1.y;
        sA[ka + 6][ra] = la1.z; sA[ka + 7][ra] = la1.w;
        *(float4*)&sB1[kb][nb] = lb1;
        *(float4*)&sB2[kb][nb] = lb2;
        __syncthreads();
        if (kt + 16 < D_) {
            const float* ap = aptr + kt + 16;
            la0 = aok ? *(const float4*)(ap)     : make_float4(0, 0, 0, 0);
            la1 = aok ? *(const float4*)(ap + 4) : make_float4(0, 0, 0, 0);
            b1ptr += bstep; b2ptr += bstep;
            lb1 = *(const float4*)b1ptr;
            lb2 = *(const float4*)b2ptr;
        }
#pragma unroll
        for (int k = 0; k < 16; k++) {
            float4 a0  = *(const float4*)&sA[k][ty * 8];
            float4 a1  = *(const float4*)&sA[k][ty * 8 + 4];
            float4 bv1 = *(const float4*)&sB1[k][tx * 4];
            float4 bv2 = *(const float4*)&sB2[k][tx * 4];
            ull b1lo = pack2(bv1.x, bv1.y), b1hi = pack2(bv1.z, bv1.w);
            ull b2lo = pack2(bv2.x, bv2.y), b2hi = pack2(bv2.z, bv2.w);
            float av[8] = {a0.x, a0.y, a0.z, a0.w, a1.x, a1.y, a1.z, a1.w};
#pragma unroll
            for (int i = 0; i < 8; i++) {
                ull a2 = pack2(av[i], av[i]);
                ffma2(c1[i][0], a2, b1lo);
                ffma2(c1[i][1], a2, b1hi);
                ffma2(c2[i][0], a2, b2lo);
                ffma2(c2[i][1], a2, b2hi);
            }
        }
    }

#pragma unroll
    for (int i = 0; i < 8; i++) {
        int m = m0 + ty * 8 + i;
        if (m < M) {
            float2 gA = unpack2(c1[i][0]);
            float2 gB = unpack2(c1[i][1]);
            float2 uA = unpack2(c2[i][0]);
            float2 uB = unpack2(c2[i][1]);
            float4 o;
            o.x = gA.x / (1.f + expf(-gA.x)) * uA.x;
            o.y = gA.y / (1.f + expf(-gA.y)) * uA.y;
            o.z = gB.x / (1.f + expf(-gB.x)) * uB.x;
            o.w = gB.y / (1.f + expf(-gB.y)) * uB.y;
            *(float4*)(g_hbuf + (size_t)(base + m) * Nn + n0 + tx * 4) = o;
        }
    }
}

// ---------------------------------------------------------------------------
// Down projection: hbuf @ Wd.  Shared: plain store (initializes out).
// Routed: scale by gate, atomicAdd-scatter to out[token].
// ---------------------------------------------------------------------------
template<bool ROUTED>
__global__ void __launch_bounds__(256, 2)
down_kernel(const float* __restrict__ Wd, float* __restrict__ out, int Kk)
{
    int e    = ROUTED ? blockIdx.z   : 0;
    int M    = ROUTED ? g_counts[e]  : N_;
    int base = ROUTED ? g_offsets[e] : 0;
    int m0 = blockIdx.x * 128;
    if (m0 >= M) return;
    int n0 = blockIdx.y * 64;
    const float* B = Wd + (ROUTED ? (size_t)e * H_ * D_ : 0);

    __shared__ float sA[16][128];
    __shared__ float sB[16][64];

    int tid = threadIdx.x;
    int ra = tid >> 1;
    int ka = (tid & 1) * 8;
    int gm = m0 + ra;
    bool aok = gm < M;
    const float* aptr = g_hbuf + (size_t)(base + (aok ? gm : 0)) * Kk + ka;

    int kb = tid >> 4;
    int nb = (tid & 15) * 4;
    const float* bptr = B + (size_t)kb * D_ + n0 + nb;
    size_t bstep = (size_t)16 * D_;

    int ty = tid >> 4;
    int tx = tid & 15;

    ull c[8][2];
#pragma unroll
    for (int i = 0; i < 8; i++) { c[i][0] = c[i][1] = 0ull; }

    float4 la0, la1, lb;
    la0 = aok ? *(const float4*)(aptr)     : make_float4(0, 0, 0, 0);
    la1 = aok ? *(const float4*)(aptr + 4) : make_float4(0, 0, 0, 0);
    lb  = *(const float4*)bptr;

    for (int kt = 0; kt < Kk; kt += 16) {
        __syncthreads();
        sA[ka + 0][ra] = la0.x; sA[ka + 1][ra] = la0.y;
        sA[ka + 2][ra] = la0.z; sA[ka + 3][ra] = la0.w;
        sA[ka + 4][ra] = la1.x; sA[ka + 5][ra] = la1.y;
        sA[ka + 6][ra] = la1.z; sA[ka + 7][ra] = la1.w;
        *(float4*)&sB[kb][nb] = lb;
        __syncthreads();
        if (kt + 16 < Kk) {
            const float* ap = aptr + kt + 16;
            la0 = aok ? *(const float4*)(ap)     : make_float4(0, 0, 0, 0);
            la1 = aok ? *(const float4*)(ap + 4) : make_float4(0, 0, 0, 0);
            bptr += bstep;
            lb = *(const float4*)bptr;
        }
#pragma unroll
        for (int k = 0; k < 16; k++) {
            float4 a0 = *(const float4*)&sA[k][ty * 8];
            float4 a1 = *(const float4*)&sA[k][ty * 8 + 4];
            float4 bv = *(const float4*)&sB[k][tx * 4];
            ull blo = pack2(bv.x, bv.y), bhi = pack2(bv.z, bv.w);
            float av[8] = {a0.x, a0.y, a0.z, a0.w, a1.x, a1.y, a1.z, a1.w};
#pragma unroll
            for (int i = 0; i < 8; i++) {
                ull a2 = pack2(av[i], av[i]);
                ffma2(c[i][0], a2, blo);
                ffma2(c[i][1], a2, bhi);
            }
        }
    }

#pragma unroll
    for (int i = 0; i < 8; i++) {
        int m = m0 + ty * 8 + i;
        if (m < M) {
            float2 vA = unpack2(c[i][0]);
            float2 vB = unpack2(c[i][1]);
            if (ROUTED) {
                int r = base + m;
                float gt = g_pgate[r];
                float* op = out + (size_t)g_perm[r] * D_ + n0 + tx * 4;
                atomicAdd(op + 0, vA.x * gt);
                atomicAdd(op + 1, vA.y * gt);
                atomicAdd(op + 2, vB.x * gt);
                atomicAdd(op + 3, vB.y * gt);
            } else {
                *(float4*)(out + (size_t)m * D_ + n0 + tx * 4) =
                    make_float4(vA.x, vA.y, vB.x, vB.y);
            }
        }
    }
}

// ---------------------------------------------------------------------------
extern "C" void kernel_launch(void* const* d_in, const int* in_sizes, int n_in,
                              void* d_out, int out_size) {
    const float* x  = (const float*)d_in[0];
    const float* rw = (const float*)d_in[1];
    const float* wg = (const float*)d_in[2];
    const float* wu = (const float*)d_in[3];
    const float* wd = (const float*)d_in[4];
    const float* sg = (const float*)d_in[5];
    const float* su = (const float*)d_in[6];
    const float* sd = (const float*)d_in[7];
    float* out = (float*)d_out;

    router_kernel<<<N_ / 8, 256>>>(x, rw);
    build_lists_kernel<<<1, 256>>>();

    // Shared expert first: down pass writes (initializes) every out element.
    gateup_kernel<false><<<dim3(N_ / 128, HS_ / 64, 1), 256>>>(x, sg, su, HS_);
    down_kernel<false><<<dim3(N_ / 128, D_ / 64, 1), 256>>>(sd, out, HS_);

    // Routed experts: gathered grouped GEMMs, atomic scatter-add on top.
    gateup_kernel<true><<<dim3(N_ / 128, H_ / 64, E_), 256>>>(x, wg, wu, H_);
    down_kernel<true><<<dim3(N_ / 128, D_ / 64, E_), 256>>>(wd, out, H_);
}

// round 3
// speedup vs baseline: 1.9479x; 1.9479x over previous
#include <cuda_runtime.h>
#include <cuda_bf16.h>
#include <cstdint>

#define D_  2048
#define H_  1408
#define HS_ 2816
#define E_  8
#define N_  4096
#define NK_ (2*N_)

typedef __nv_bfloat16 bf16;

constexpr size_t EDH = (size_t)E_ * D_ * H_;
constexpr size_t DHS = (size_t)D_ * HS_;
constexpr size_t XSZ = (size_t)N_ * D_;
constexpr size_t HBUFSZ = 11534336;  // max(4096*2816, 8192*1408)

// -------- static scratch (no runtime allocation allowed) --------
__device__ bf16 g_wg_hi[EDH], g_wg_lo[EDH];   // transposed [E][H][D]
__device__ bf16 g_wu_hi[EDH], g_wu_lo[EDH];   // transposed [E][H][D]
__device__ bf16 g_wd_hi[EDH], g_wd_lo[EDH];   // transposed [E][D][H]
__device__ bf16 g_sg_hi[DHS], g_sg_lo[DHS];   // transposed [HS][D]
__device__ bf16 g_su_hi[DHS], g_su_lo[DHS];   // transposed [HS][D]
__device__ bf16 g_sd_hi[DHS], g_sd_lo[DHS];   // transposed [D][HS]
__device__ bf16 g_x_hi[XSZ], g_x_lo[XSZ];     // [N][D]
__device__ bf16 g_h_hi[HBUFSZ], g_h_lo[HBUFSZ];
__device__ int   g_perm[NK_];
__device__ float g_pgate[NK_];
__device__ int   g_counts[E_];
__device__ int   g_offsets[E_ + 1];
__device__ int   g_gidx[NK_];
__device__ float g_gval[NK_];

// -------- helpers --------
__device__ __forceinline__ void split_bf(float v, bf16& h, bf16& l) {
    h = __float2bfloat16(v);
    l = __float2bfloat16(v - __bfloat162float(h));
}
__device__ __forceinline__ void cpa(uint32_t d, const void* s) {
    asm volatile("cp.async.cg.shared.global [%0], [%1], 16;" :: "r"(d), "l"(s));
}
__device__ __forceinline__ void ldmx4(uint32_t* r, uint32_t a) {
    asm volatile("ldmatrix.sync.aligned.m8n8.x4.shared.b16 {%0,%1,%2,%3}, [%4];"
                 : "=r"(r[0]), "=r"(r[1]), "=r"(r[2]), "=r"(r[3]) : "r"(a));
}
__device__ __forceinline__ void mma16816(float* c, const uint32_t* a, const uint32_t* b) {
    asm volatile(
        "mma.sync.aligned.m16n8k16.row.col.f32.bf16.bf16.f32 "
        "{%0,%1,%2,%3},{%4,%5,%6,%7},{%8,%9},{%0,%1,%2,%3};"
        : "+f"(c[0]), "+f"(c[1]), "+f"(c[2]), "+f"(c[3])
        : "r"(a[0]), "r"(a[1]), "r"(a[2]), "r"(a[3]), "r"(b[0]), "r"(b[1]));
}

// -------- conversion kernels --------
// src [R][C] fp32 (C contiguous) -> dst hi/lo [C][R] bf16, batched over z.
__global__ void tconv(const float* __restrict__ src, bf16* __restrict__ dhi,
                      bf16* __restrict__ dlo, int R, int C) {
    __shared__ float t[32][33];
    size_t zo = (size_t)blockIdx.z * R * C;
    src += zo; dhi += zo; dlo += zo;
    int c0 = blockIdx.x * 32, r0 = blockIdx.y * 32;
    int tx = threadIdx.x, ty = threadIdx.y;
#pragma unroll
    for (int i = 0; i < 4; i++)
        t[ty + 8 * i][tx] = src[(size_t)(r0 + ty + 8 * i) * C + c0 + tx];
    __syncthreads();
#pragma unroll
    for (int i = 0; i < 4; i++) {
        float v = t[tx][ty + 8 * i];
        bf16 h, l; split_bf(v, h, l);
        size_t o = (size_t)(c0 + ty + 8 * i) * R + r0 + tx;
        dhi[o] = h; dlo[o] = l;
    }
}

__global__ void xconv(const float* __restrict__ x) {
    size_t i = (size_t)blockIdx.x * blockDim.x + threadIdx.x;
    float4 v = ((const float4*)x)[i];
    bf16 h0, l0, h1, l1, h2, l2, h3, l3;
    split_bf(v.x, h0, l0); split_bf(v.y, h1, l1);
    split_bf(v.z, h2, l2); split_bf(v.w, h3, l3);
    __nv_bfloat162* ph = (__nv_bfloat162*)(g_x_hi + 4 * i);
    __nv_bfloat162* pl = (__nv_bfloat162*)(g_x_lo + 4 * i);
    ph[0] = __halves2bfloat162(h0, h1); ph[1] = __halves2bfloat162(h2, h3);
    pl[0] = __halves2bfloat162(l0, l1); pl[1] = __halves2bfloat162(l2, l3);
}

// -------- router --------
__global__ void router_kernel(const float* __restrict__ x, const float* __restrict__ rw) {
    int gw = (blockIdx.x * blockDim.x + threadIdx.x) >> 5;
    int lane = threadIdx.x & 31;
    if (gw >= N_) return;
    const float* xr = x + (size_t)gw * D_;
    float acc[E_];
#pragma unroll
    for (int e = 0; e < E_; e++) acc[e] = 0.f;
    for (int d = lane * 4; d < D_; d += 128) {
        float4 xv = *(const float4*)(xr + d);
#pragma unroll
        for (int e = 0; e < E_; e++) {
            float4 wv = *(const float4*)(rw + e * D_ + d);
            acc[e] += xv.x * wv.x + xv.y * wv.y + xv.z * wv.z + xv.w * wv.w;
        }
    }
#pragma unroll
    for (int e = 0; e < E_; e++) {
#pragma unroll
        for (int o = 16; o > 0; o >>= 1)
            acc[e] += __shfl_down_sync(0xffffffffu, acc[e], o);
    }
    if (lane == 0) {
        float mx = acc[0];
#pragma unroll
        for (int e = 1; e < E_; e++) mx = fmaxf(mx, acc[e]);
        float p[E_], s = 0.f;
#pragma unroll
        for (int e = 0; e < E_; e++) { p[e] = expf(acc[e] - mx); s += p[e]; }
        int i1 = 0;
#pragma unroll
        for (int e = 1; e < E_; e++) if (p[e] > p[i1]) i1 = e;
        int i2 = (i1 == 0) ? 1 : 0;
#pragma unroll
        for (int e = 0; e < E_; e++) if (e != i1 && p[e] > p[i2]) i2 = e;
        float g1 = p[i1] / s, g2 = p[i2] / s;
        float den = g1 + g2 + 1e-20f;
        g_gidx[2 * gw]     = i1; g_gval[2 * gw]     = g1 / den;
        g_gidx[2 * gw + 1] = i2; g_gval[2 * gw + 1] = g2 / den;
    }
}

__global__ void build_lists_kernel() {
    __shared__ int scnt[E_];
    __shared__ int soff[E_];
    int wid = threadIdx.x >> 5, lane = threadIdx.x & 31;
    if (wid < E_) {
        int c = 0;
        for (int base = 0; base < NK_; base += 32) {
            int flag = (g_gidx[base + lane] == wid);
            c += __popc(__ballot_sync(0xffffffffu, flag));
        }
        if (lane == 0) scnt[wid] = c;
    }
    __syncthreads();
    if (threadIdx.x == 0) {
        int s = 0;
        for (int e = 0; e < E_; e++) {
            soff[e] = s; g_offsets[e] = s; g_counts[e] = scnt[e]; s += scnt[e];
        }
        g_offsets[E_] = s;
    }
    __syncthreads();
    if (wid < E_) {
        int pos = soff[wid];
        for (int base = 0; base < NK_; base += 32) {
            int t = base + lane;
            int flag = (g_gidx[t] == wid);
            unsigned m = __ballot_sync(0xffffffffu, flag);
            if (flag) {
                int off = __popc(m & ((1u << lane) - 1u));
                g_perm[pos + off]  = t >> 1;
                g_pgate[pos + off] = g_gval[t];
            }
            pos += __popc(m);
        }
    }
}

// ---------------------------------------------------------------------------
// Fused gate/up tensor-core GEMM + SiLU epilogue -> g_h_hi/lo.
// BM=128 BN=64 BK=32, 8 warps (4m x 2n), bf16x3 split, cp.async double buffer.
// Stage layout (bytes): Ahi 0, Alo 10240, Bg_hi 20480, Bg_lo 25600,
//                       Bu_hi 30720, Bu_lo 35840. Stage stride 40960. Rows 80B.
// ---------------------------------------------------------------------------
template<bool ROUTED>
__global__ void __launch_bounds__(256)
gateup_mma(int Nn) {
    int e    = ROUTED ? blockIdx.z : 0;
    int M    = ROUTED ? g_counts[e] : N_;
    int base = ROUTED ? g_offsets[e] : 0;
    int m0 = blockIdx.x * 128;
    if (m0 >= M) return;
    int n0 = blockIdx.y * 64;

    size_t eoff = ROUTED ? (size_t)e * D_ * H_ : 0;
    const bf16* Bgh = (ROUTED ? g_wg_hi : g_sg_hi) + eoff;
    const bf16* Bgl = (ROUTED ? g_wg_lo : g_sg_lo) + eoff;
    const bf16* Buh = (ROUTED ? g_wu_hi : g_su_hi) + eoff;
    const bf16* Bul = (ROUTED ? g_wu_lo : g_su_lo) + eoff;

    extern __shared__ char smem[];
    __shared__ int stok[128];
    int tid = threadIdx.x;
    if (tid < 128) {
        int r = m0 + tid; if (r > M - 1) r = M - 1;
        stok[tid] = ROUTED ? g_perm[base + r] : r;
    }
    __syncthreads();

    int row4 = tid >> 2;          // 0..63
    int kq   = (tid & 3) * 16;    // byte offset in 64B chunk
    const char* sA0h = (const char*)(g_x_hi + (size_t)stok[row4] * D_) + kq;
    const char* sA1h = (const char*)(g_x_hi + (size_t)stok[row4 + 64] * D_) + kq;
    const char* sA0l = (const char*)(g_x_lo + (size_t)stok[row4] * D_) + kq;
    const char* sA1l = (const char*)(g_x_lo + (size_t)stok[row4 + 64] * D_) + kq;
    const char* pBgh = (const char*)(Bgh + (size_t)(n0 + row4) * D_) + kq;
    const char* pBgl = (const char*)(Bgl + (size_t)(n0 + row4) * D_) + kq;
    const char* pBuh = (const char*)(Buh + (size_t)(n0 + row4) * D_) + kq;
    const char* pBul = (const char*)(Bul + (size_t)(n0 + row4) * D_) + kq;

    uint32_t sb = (uint32_t)__cvta_generic_to_shared(smem);
    uint32_t dA0 = sb + row4 * 80 + kq;
    uint32_t dA1 = sb + (row4 + 64) * 80 + kq;
    uint32_t dB  = sb + row4 * 80 + kq;

    auto issue = [&](int stage, int kt) {
        uint32_t so = stage * 40960;
        size_t ko = (size_t)kt * 64;
        cpa(dA0 + so,         sA0h + ko);
        cpa(dA1 + so,         sA1h + ko);
        cpa(dA0 + so + 10240, sA0l + ko);
        cpa(dA1 + so + 10240, sA1l + ko);
        cpa(dB + so + 20480,  pBgh + ko);
        cpa(dB + so + 25600,  pBgl + ko);
        cpa(dB + so + 30720,  pBuh + ko);
        cpa(dB + so + 35840,  pBul + ko);
        asm volatile("cp.async.commit_group;");
    };

    int lane = tid & 31, wid = tid >> 5;
    int wm = (wid & 3) * 32;
    int wn = (wid >> 2) * 32;
    int grp = lane >> 3, lr = lane & 7;
    uint32_t aoff[2], boff[2];
#pragma unroll
    for (int mf = 0; mf < 2; mf++)
        aoff[mf] = (uint32_t)((wm + mf * 16 + (grp & 1) * 8 + lr) * 80 + (grp >> 1) * 16);
#pragma unroll
    for (int nf2 = 0; nf2 < 2; nf2++)
        boff[nf2] = (uint32_t)((wn + nf2 * 16 + (grp >> 1) * 8 + lr) * 80 + (grp & 1) * 16);

    float cg[2][4][4], cu[2][4][4];
#pragma unroll
    for (int a = 0; a < 2; a++)
#pragma unroll
    for (int b = 0; b < 4; b++)
#pragma unroll
    for (int c = 0; c < 4; c++) { cg[a][b][c] = 0.f; cu[a][b][c] = 0.f; }

    const int KI = D_ / 32;
    issue(0, 0);
    for (int kt = 0; kt < KI; kt++) {
        int cur = kt & 1;
        if (kt + 1 < KI) {
            issue(cur ^ 1, kt + 1);
            asm volatile("cp.async.wait_group 1;");
        } else {
            asm volatile("cp.async.wait_group 0;");
        }
        __syncthreads();
        uint32_t st = sb + cur * 40960;
#pragma unroll
        for (int ks = 0; ks < 2; ks++) {
            uint32_t kb = ks * 32;
            uint32_t ah[2][4], al[2][4];
            uint32_t bgh[2][4], bgl[2][4], buh[2][4], bul[2][4];
#pragma unroll
            for (int mf = 0; mf < 2; mf++) {
                ldmx4(ah[mf], st + aoff[mf] + kb);
                ldmx4(al[mf], st + 10240 + aoff[mf] + kb);
            }
#pragma unroll
            for (int nf2 = 0; nf2 < 2; nf2++) {
                ldmx4(bgh[nf2], st + 20480 + boff[nf2] + kb);
                ldmx4(bgl[nf2], st + 25600 + boff[nf2] + kb);
                ldmx4(buh[nf2], st + 30720 + boff[nf2] + kb);
                ldmx4(bul[nf2], st + 35840 + boff[nf2] + kb);
            }
#pragma unroll
            for (int mf = 0; mf < 2; mf++)
#pragma unroll
            for (int nf2 = 0; nf2 < 2; nf2++)
#pragma unroll
            for (int j = 0; j < 2; j++) {
                int nf = nf2 * 2 + j;
                mma16816(cg[mf][nf], ah[mf], &bgh[nf2][2 * j]);
                mma16816(cg[mf][nf], al[mf], &bgh[nf2][2 * j]);
                mma16816(cg[mf][nf], ah[mf], &bgl[nf2][2 * j]);
                mma16816(cu[mf][nf], ah[mf], &buh[nf2][2 * j]);
                mma16816(cu[mf][nf], al[mf], &buh[nf2][2 * j]);
                mma16816(cu[mf][nf], ah[mf], &bul[nf2][2 * j]);
            }
        }
        __syncthreads();
    }

#pragma unroll
    for (int mf = 0; mf < 2; mf++)
#pragma unroll
    for (int nf = 0; nf < 4; nf++) {
        int r = m0 + wm + mf * 16 + (lane >> 2);
        int c = n0 + wn + nf * 8 + (lane & 3) * 2;
#pragma unroll
        for (int h = 0; h < 2; h++) {
            int rr = r + h * 8;
            if (rr < M) {
                float gv0 = cg[mf][nf][2 * h],     gv1 = cg[mf][nf][2 * h + 1];
                float uv0 = cu[mf][nf][2 * h],     uv1 = cu[mf][nf][2 * h + 1];
                float h0 = gv0 / (1.f + expf(-gv0)) * uv0;
                float h1 = gv1 / (1.f + expf(-gv1)) * uv1;
                size_t o = (size_t)(base + rr) * Nn + c;
                bf16 hh0, hl0, hh1, hl1;
                split_bf(h0, hh0, hl0); split_bf(h1, hh1, hl1);
                *(__nv_bfloat162*)(g_h_hi + o) = __halves2bfloat162(hh0, hh1);
                *(__nv_bfloat162*)(g_h_lo + o) = __halves2bfloat162(hl0, hl1);
            }
        }
    }
}

// ---------------------------------------------------------------------------
// Down projection GEMM. Stage: Ahi 0, Alo 10240, Bhi 20480, Blo 25600;
// stage stride 30720.
// ---------------------------------------------------------------------------
template<bool ROUTED>
__global__ void __launch_bounds__(256)
down_mma(float* __restrict__ out, int Kk) {
    int e    = ROUTED ? blockIdx.z : 0;
    int M    = ROUTED ? g_counts[e] : N_;
    int base = ROUTED ? g_offsets[e] : 0;
    int m0 = blockIdx.x * 128;
    if (m0 >= M) return;
    int n0 = blockIdx.y * 64;

    size_t eoff = ROUTED ? (size_t)e * D_ * H_ : 0;
    const bf16* Bh = (ROUTED ? g_wd_hi : g_sd_hi) + eoff;
    const bf16* Bl = (ROUTED ? g_wd_lo : g_sd_lo) + eoff;

    extern __shared__ char smem[];
    int tid = threadIdx.x;
    int row4 = tid >> 2;
    int kq   = (tid & 3) * 16;
    int ra0 = m0 + row4;      if (ra0 > M - 1) ra0 = M - 1;
    int ra1 = m0 + row4 + 64; if (ra1 > M - 1) ra1 = M - 1;
    const char* sA0h = (const char*)(g_h_hi + (size_t)(base + ra0) * Kk) + kq;
    const char* sA1h = (const char*)(g_h_hi + (size_t)(base + ra1) * Kk) + kq;
    const char* sA0l = (const char*)(g_h_lo + (size_t)(base + ra0) * Kk) + kq;
    const char* sA1l = (const char*)(g_h_lo + (size_t)(base + ra1) * Kk) + kq;
    const char* pBh = (const char*)(Bh + (size_t)(n0 + row4) * Kk) + kq;
    const char* pBl = (const char*)(Bl + (size_t)(n0 + row4) * Kk) + kq;

    uint32_t sb = (uint32_t)__cvta_generic_to_shared(smem);
    uint32_t dA0 = sb + row4 * 80 + kq;
    uint32_t dA1 = sb + (row4 + 64) * 80 + kq;
    uint32_t dB  = sb + row4 * 80 + kq;

    auto issue = [&](int stage, int kt) {
        uint32_t so = stage * 30720;
        size_t ko = (size_t)kt * 64;
        cpa(dA0 + so,         sA0h + ko);
        cpa(dA1 + so,         sA1h + ko);
        cpa(dA0 + so + 10240, sA0l + ko);
        cpa(dA1 + so + 10240, sA1l + ko);
        cpa(dB + so + 20480,  pBh + ko);
        cpa(dB + so + 25600,  pBl + ko);
        asm volatile("cp.async.commit_group;");
    };

    int lane = tid & 31, wid = tid >> 5;
    int wm = (wid & 3) * 32;
    int wn = (wid >> 2) * 32;
    int grp = lane >> 3, lr = lane & 7;
    uint32_t aoff[2], boff[2];
#pragma unroll
    for (int mf = 0; mf < 2; mf++)
        aoff[mf] = (uint32_t)((wm + mf * 16 + (grp & 1) * 8 + lr) * 80 + (grp >> 1) * 16);
#pragma unroll
    for (int nf2 = 0; nf2 < 2; nf2++)
        boff[nf2] = (uint32_t)((wn + nf2 * 16 + (grp >> 1) * 8 + lr) * 80 + (grp & 1) * 16);

    float cd[2][4][4];
#pragma unroll
    for (int a = 0; a < 2; a++)
#pragma unroll
    for (int b = 0; b < 4; b++)
#pragma unroll
    for (int c = 0; c < 4; c++) cd[a][b][c] = 0.f;

    const int KI = Kk / 32;
    issue(0, 0);
    for (int kt = 0; kt < KI; kt++) {
        int cur = kt & 1;
        if (kt + 1 < KI) {
            issue(cur ^ 1, kt + 1);
            asm volatile("cp.async.wait_group 1;");
        } else {
            asm volatile("cp.async.wait_group 0;");
        }
        __syncthreads();
        uint32_t st = sb + cur * 30720;
#pragma unroll
        for (int ks = 0; ks < 2; ks++) {
            uint32_t kb = ks * 32;
            uint32_t ah[2][4], al[2][4], bh[2][4], bl[2][4];
#pragma unroll
            for (int mf = 0; mf < 2; mf++) {
                ldmx4(ah[mf], st + aoff[mf] + kb);
                ldmx4(al[mf], st + 10240 + aoff[mf] + kb);
            }
#pragma unroll
            for (int nf2 = 0; nf2 < 2; nf2++) {
                ldmx4(bh[nf2], st + 20480 + boff[nf2] + kb);
                ldmx4(bl[nf2], st + 25600 + boff[nf2] + kb);
            }
#pragma unroll
            for (int mf = 0; mf < 2; mf++)
#pragma unroll
            for (int nf2 = 0; nf2 < 2; nf2++)
#pragma unroll
            for (int j = 0; j < 2; j++) {
                int nf = nf2 * 2 + j;
                mma16816(cd[mf][nf], ah[mf], &bh[nf2][2 * j]);
                mma16816(cd[mf][nf], al[mf], &bh[nf2][2 * j]);
                mma16816(cd[mf][nf], ah[mf], &bl[nf2][2 * j]);
            }
        }
        __syncthreads();
    }

#pragma unroll
    for (int mf = 0; mf < 2; mf++)
#pragma unroll
    for (int nf = 0; nf < 4; nf++) {
        int r = m0 + wm + mf * 16 + (lane >> 2);
        int c = n0 + wn + nf * 8 + (lane & 3) * 2;
#pragma unroll
        for (int h = 0; h < 2; h++) {
            int rr = r + h * 8;
            if (rr < M) {
                float v0 = cd[mf][nf][2 * h], v1 = cd[mf][nf][2 * h + 1];
                if (ROUTED) {
                    int p = base + rr;
                    float gt = g_pgate[p];
                    float* op = out + (size_t)g_perm[p] * D_ + c;
                    atomicAdd(op,     v0 * gt);
                    atomicAdd(op + 1, v1 * gt);
                } else {
                    *(float2*)(out + (size_t)rr * D_ + c) = make_float2(v0, v1);
                }
            }
        }
    }
}

// ---------------------------------------------------------------------------
extern "C" void kernel_launch(void* const* d_in, const int* in_sizes, int n_in,
                              void* d_out, int out_size) {
    const float* x  = (const float*)d_in[0];
    const float* rw = (const float*)d_in[1];
    const float* wg = (const float*)d_in[2];
    const float* wu = (const float*)d_in[3];
    const float* wd = (const float*)d_in[4];
    const float* sg = (const float*)d_in[5];
    const float* su = (const float*)d_in[6];
    const float* sd = (const float*)d_in[7];
    float* out = (float*)d_out;

    cudaFuncSetAttribute(gateup_mma<false>, cudaFuncAttributeMaxDynamicSharedMemorySize, 81920);
    cudaFuncSetAttribute(gateup_mma<true>,  cudaFuncAttributeMaxDynamicSharedMemorySize, 81920);
    cudaFuncSetAttribute(down_mma<false>,   cudaFuncAttributeMaxDynamicSharedMemorySize, 61440);
    cudaFuncSetAttribute(down_mma<true>,    cudaFuncAttributeMaxDynamicSharedMemorySize, 61440);

    bf16 *wg_hi, *wg_lo, *wu_hi, *wu_lo, *wd_hi, *wd_lo;
    bf16 *sg_hi, *sg_lo, *su_hi, *su_lo, *sd_hi, *sd_lo;
    cudaGetSymbolAddress((void**)&wg_hi, g_wg_hi); cudaGetSymbolAddress((void**)&wg_lo, g_wg_lo);
    cudaGetSymbolAddress((void**)&wu_hi, g_wu_hi); cudaGetSymbolAddress((void**)&wu_lo, g_wu_lo);
    cudaGetSymbolAddress((void**)&wd_hi, g_wd_hi); cudaGetSymbolAddress((void**)&wd_lo, g_wd_lo);
    cudaGetSymbolAddress((void**)&sg_hi, g_sg_hi); cudaGetSymbolAddress((void**)&sg_lo, g_sg_lo);
    cudaGetSymbolAddress((void**)&su_hi, g_su_hi); cudaGetSymbolAddress((void**)&su_lo, g_su_lo);
    cudaGetSymbolAddress((void**)&sd_hi, g_sd_hi); cudaGetSymbolAddress((void**)&sd_lo, g_sd_lo);

    dim3 tb(32, 8);
    // weight conversion + transpose to [N][K], hi/lo split
    tconv<<<dim3(H_ / 32, D_ / 32, E_), tb>>>(wg, wg_hi, wg_lo, D_, H_);
    tconv<<<dim3(H_ / 32, D_ / 32, E_), tb>>>(wu, wu_hi, wu_lo, D_, H_);
    tconv<<<dim3(D_ / 32, H_ / 32, E_), tb>>>(wd, wd_hi, wd_lo, H_, D_);
    tconv<<<dim3(HS_ / 32, D_ / 32, 1), tb>>>(sg, sg_hi, sg_lo, D_, HS_);
    tconv<<<dim3(HS_ / 32, D_ / 32, 1), tb>>>(su, su_hi, su_lo, D_, HS_);
    tconv<<<dim3(D_ / 32, HS_ / 32, 1), tb>>>(sd, sd_hi, sd_lo, HS_, D_);
    xconv<<<(N_ * D_ / 4) / 256, 256>>>(x);

    router_kernel<<<N_ / 8, 256>>>(x, rw);
    build_lists_kernel<<<1, 256>>>();

    // Shared expert first: its down pass initializes every out element.
    gateup_mma<false><<<dim3(N_ / 128, HS_ / 64, 1), 256, 81920>>>(HS_);
    down_mma<false><<<dim3(N_ / 128, D_ / 64, 1), 256, 61440>>>(out, HS_);

    // Routed experts: gathered grouped GEMMs + atomic scatter-add.
    gateup_mma<true><<<dim3(N_ / 128, H_ / 64, E_), 256, 81920>>>(H_);
    down_mma<true><<<dim3(N_ / 128, D_ / 64, E_), 256, 61440>>>(out, H_);
}

// round 5
// speedup vs baseline: 2.0067x; 1.0302x over previous
#include <cuda_runtime.h>
#include <cuda_bf16.h>
#include <cstdint>

#define D_  2048
#define H_  1408
#define HS_ 2816
#define E_  8
#define N_  4096
#define NK_ (2*N_)

typedef __nv_bfloat16 bf16;

constexpr size_t EDH = (size_t)E_ * D_ * H_;
constexpr size_t DHS = (size_t)D_ * HS_;
constexpr size_t XSZ = (size_t)N_ * D_;
constexpr size_t HBUFSZ = 11534336;  // max(4096*2816, 8192*1408)

// -------- static scratch (no runtime allocation allowed) --------
__device__ bf16 g_wg_hi[EDH], g_wg_lo[EDH];   // transposed [E][H][D]
__device__ bf16 g_wu_hi[EDH], g_wu_lo[EDH];   // transposed [E][H][D]
__device__ bf16 g_wd_hi[EDH], g_wd_lo[EDH];   // transposed [E][D][H]
__device__ bf16 g_sg_hi[DHS], g_sg_lo[DHS];   // transposed [HS][D]
__device__ bf16 g_su_hi[DHS], g_su_lo[DHS];   // transposed [HS][D]
__device__ bf16 g_sd_hi[DHS], g_sd_lo[DHS];   // transposed [D][HS]
__device__ bf16 g_x_hi[XSZ], g_x_lo[XSZ];     // [N][D]
__device__ bf16 g_h_hi[HBUFSZ], g_h_lo[HBUFSZ];
__device__ int   g_perm[NK_];
__device__ float g_pgate[NK_];
__device__ int   g_counts[E_];
__device__ int   g_offsets[E_ + 1];
__device__ int   g_gidx[NK_];
__device__ float g_gval[NK_];

// -------- helpers --------
__device__ __forceinline__ void split_bf(float v, bf16& h, bf16& l) {
    h = __float2bfloat16(v);
    l = __float2bfloat16(v - __bfloat162float(h));
}
__device__ __forceinline__ void cpa(uint32_t d, const void* s) {
    asm volatile("cp.async.cg.shared.global [%0], [%1], 16;" :: "r"(d), "l"(s));
}
__device__ __forceinline__ void ldmx4(uint32_t* r, uint32_t a) {
    asm volatile("ldmatrix.sync.aligned.m8n8.x4.shared.b16 {%0,%1,%2,%3}, [%4];"
                 : "=r"(r[0]), "=r"(r[1]), "=r"(r[2]), "=r"(r[3]) : "r"(a));
}
__device__ __forceinline__ void mma16816(float* c, const uint32_t* a, const uint32_t* b) {
    asm volatile(
        "mma.sync.aligned.m16n8k16.row.col.f32.bf16.bf16.f32 "
        "{%0,%1,%2,%3},{%4,%5,%6,%7},{%8,%9},{%0,%1,%2,%3};"
        : "+f"(c[0]), "+f"(c[1]), "+f"(c[2]), "+f"(c[3])
        : "r"(a[0]), "r"(a[1]), "r"(a[2]), "r"(a[3]), "r"(b[0]), "r"(b[1]));
}

// -------- conversion kernels --------
__global__ void tconv(const float* __restrict__ src, bf16* __restrict__ dhi,
                      bf16* __restrict__ dlo, int R, int C) {
    __shared__ float t[32][33];
    size_t zo = (size_t)blockIdx.z * R * C;
    src += zo; dhi += zo; dlo += zo;
    int c0 = blockIdx.x * 32, r0 = blockIdx.y * 32;
    int tx = threadIdx.x, ty = threadIdx.y;
#pragma unroll
    for (int i = 0; i < 4; i++)
        t[ty + 8 * i][tx] = src[(size_t)(r0 + ty + 8 * i) * C + c0 + tx];
    __syncthreads();
#pragma unroll
    for (int i = 0; i < 4; i++) {
        float v = t[tx][ty + 8 * i];
        bf16 h, l; split_bf(v, h, l);
        size_t o = (size_t)(c0 + ty + 8 * i) * R + r0 + tx;
        dhi[o] = h; dlo[o] = l;
    }
}

__global__ void xconv(const float* __restrict__ x) {
    size_t i = (size_t)blockIdx.x * blockDim.x + threadIdx.x;
    float4 v = ((const float4*)x)[i];
    bf16 h0, l0, h1, l1, h2, l2, h3, l3;
    split_bf(v.x, h0, l0); split_bf(v.y, h1, l1);
    split_bf(v.z, h2, l2); split_bf(v.w, h3, l3);
    __nv_bfloat162* ph = (__nv_bfloat162*)(g_x_hi + 4 * i);
    __nv_bfloat162* pl = (__nv_bfloat162*)(g_x_lo + 4 * i);
    ph[0] = __halves2bfloat162(h0, h1); ph[1] = __halves2bfloat162(h2, h3);
    pl[0] = __halves2bfloat162(l0, l1); pl[1] = __halves2bfloat162(l2, l3);
}

// -------- router + list build (proven) --------
__global__ void router_kernel(const float* __restrict__ x, const float* __restrict__ rw) {
    int gw = (blockIdx.x * blockDim.x + threadIdx.x) >> 5;
    int lane = threadIdx.x & 31;
    if (gw >= N_) return;
    const float* xr = x + (size_t)gw * D_;
    float acc[E_];
#pragma unroll
    for (int e = 0; e < E_; e++) acc[e] = 0.f;
    for (int d = lane * 4; d < D_; d += 128) {
        float4 xv = *(const float4*)(xr + d);
#pragma unroll
        for (int e = 0; e < E_; e++) {
            float4 wv = *(const float4*)(rw + e * D_ + d);
            acc[e] += xv.x * wv.x + xv.y * wv.y + xv.z * wv.z + xv.w * wv.w;
        }
    }
#pragma unroll
    for (int e = 0; e < E_; e++) {
#pragma unroll
        for (int o = 16; o > 0; o >>= 1)
            acc[e] += __shfl_down_sync(0xffffffffu, acc[e], o);
    }
    if (lane == 0) {
        float mx = acc[0];
#pragma unroll
        for (int e = 1; e < E_; e++) mx = fmaxf(mx, acc[e]);
        float p[E_], s = 0.f;
#pragma unroll
        for (int e = 0; e < E_; e++) { p[e] = expf(acc[e] - mx); s += p[e]; }
        int i1 = 0;
#pragma unroll
        for (int e = 1; e < E_; e++) if (p[e] > p[i1]) i1 = e;
        int i2 = (i1 == 0) ? 1 : 0;
#pragma unroll
        for (int e = 0; e < E_; e++) if (e != i1 && p[e] > p[i2]) i2 = e;
        float g1 = p[i1] / s, g2 = p[i2] / s;
        float den = g1 + g2 + 1e-20f;
        g_gidx[2 * gw]     = i1; g_gval[2 * gw]     = g1 / den;
        g_gidx[2 * gw + 1] = i2; g_gval[2 * gw + 1] = g2 / den;
    }
}

__global__ void build_lists_kernel() {
    __shared__ int scnt[E_];
    __shared__ int soff[E_];
    int wid = threadIdx.x >> 5, lane = threadIdx.x & 31;
    if (wid < E_) {
        int c = 0;
        for (int base = 0; base < NK_; base += 32) {
            int flag = (g_gidx[base + lane] == wid);
            c += __popc(__ballot_sync(0xffffffffu, flag));
        }
        if (lane == 0) scnt[wid] = c;
    }
    __syncthreads();
    if (threadIdx.x == 0) {
        int s = 0;
        for (int e = 0; e < E_; e++) {
            soff[e] = s; g_offsets[e] = s; g_counts[e] = scnt[e]; s += scnt[e];
        }
        g_offsets[E_] = s;
    }
    __syncthreads();
    if (wid < E_) {
        int pos = soff[wid];
        for (int base = 0; base < NK_; base += 32) {
            int t = base + lane;
            int flag = (g_gidx[t] == wid);
            unsigned m = __ballot_sync(0xffffffffu, flag);
            if (flag) {
                int off = __popc(m & ((1u << lane) - 1u));
                g_perm[pos + off]  = t >> 1;
                g_pgate[pos + off] = g_gval[t];
            }
            pos += __popc(m);
        }
    }
}

// ---------------------------------------------------------------------------
// Fused gate/up GEMM + SiLU. BM=128 BN=128 BK=32, 512 threads (16 warps,
// 4m x 4n, warp tile 32x32), bf16x3 split, cp.async double buffer.
// Stage (80B rows, 10240B/tile): Ahi 0, Alo 10240, Bg_hi 20480, Bg_lo 30720,
//   Bu_hi 40960, Bu_lo 51200. Stage stride 61440.
// ---------------------------------------------------------------------------
#define STG_GU 61440
template<bool ROUTED>
__global__ void __launch_bounds__(512)
gateup_mma(int Nn) {
    int e    = ROUTED ? blockIdx.z : 0;
    int M    = ROUTED ? g_counts[e] : N_;
    int base = ROUTED ? g_offsets[e] : 0;
    int m0 = blockIdx.x * 128;
    if (m0 >= M) return;
    int n0 = blockIdx.y * 128;

    size_t eoff = ROUTED ? (size_t)e * D_ * H_ : 0;
    const bf16* Bgh = (ROUTED ? g_wg_hi : g_sg_hi) + eoff;
    const bf16* Bgl = (ROUTED ? g_wg_lo : g_sg_lo) + eoff;
    const bf16* Buh = (ROUTED ? g_wu_hi : g_su_hi) + eoff;
    const bf16* Bul = (ROUTED ? g_wu_lo : g_su_lo) + eoff;

    extern __shared__ char smem[];
    __shared__ int stok[128];
    int tid = threadIdx.x;
    if (tid < 128) {
        int r = m0 + tid; if (r > M - 1) r = M - 1;
        stok[tid] = ROUTED ? g_perm[base + r] : r;
    }
    __syncthreads();

    int row = tid >> 2;           // 0..127
    int kq  = (tid & 3) * 16;     // byte offset within 64B of the row
    const char* pAh = (const char*)(g_x_hi + (size_t)stok[row] * D_) + kq;
    const char* pAl = (const char*)(g_x_lo + (size_t)stok[row] * D_) + kq;
    const char* pGh = (const char*)(Bgh + (size_t)(n0 + row) * D_) + kq;
    const char* pGl = (const char*)(Bgl + (size_t)(n0 + row) * D_) + kq;
    const char* pUh = (const char*)(Buh + (size_t)(n0 + row) * D_) + kq;
    const char* pUl = (const char*)(Bul + (size_t)(n0 + row) * D_) + kq;

    uint32_t sb = (uint32_t)__cvta_generic_to_shared(smem);
    uint32_t dr = sb + row * 80 + kq;

    auto issue = [&](int stage, int kt) {
        uint32_t so = stage * STG_GU;
        size_t ko = (size_t)kt * 64;
        cpa(dr + so,         pAh + ko);
        cpa(dr + so + 10240, pAl + ko);
        cpa(dr + so + 20480, pGh + ko);
        cpa(dr + so + 30720, pGl + ko);
        cpa(dr + so + 40960, pUh + ko);
        cpa(dr + so + 51200, pUl + ko);
        asm volatile("cp.async.commit_group;");
    };

    int lane = tid & 31, wid = tid >> 5;
    int wm = (wid & 3) * 32;
    int wn = (wid >> 2) * 32;
    int grp = lane >> 3, lr = lane & 7;
    uint32_t aoff[2], boff[2];
#pragma unroll
    for (int mf = 0; mf < 2; mf++)
        aoff[mf] = (uint32_t)((wm + mf * 16 + (grp & 1) * 8 + lr) * 80 + (grp >> 1) * 16);
#pragma unroll
    for (int nf2 = 0; nf2 < 2; nf2++)
        boff[nf2] = (uint32_t)((wn + nf2 * 16 + (grp >> 1) * 8 + lr) * 80 + (grp & 1) * 16);

    float cg[2][4][4], cu[2][4][4];
#pragma unroll
    for (int a = 0; a < 2; a++)
#pragma unroll
    for (int b = 0; b < 4; b++)
#pragma unroll
    for (int c = 0; c < 4; c++) { cg[a][b][c] = 0.f; cu[a][b][c] = 0.f; }

    const int KI = D_ / 32;
    issue(0, 0);
    for (int kt = 0; kt < KI; kt++) {
        int cur = kt & 1;
        if (kt + 1 < KI) {
            issue(cur ^ 1, kt + 1);
            asm volatile("cp.async.wait_group 1;");
        } else {
            asm volatile("cp.async.wait_group 0;");
        }
        __syncthreads();
        uint32_t st = sb + cur * STG_GU;
#pragma unroll
        for (int ks = 0; ks < 2; ks++) {
            uint32_t kb = ks * 32;
            uint32_t ah[2][4], al[2][4], bh[2][4], bl[2][4];
#pragma unroll
            for (int mf = 0; mf < 2; mf++) {
                ldmx4(ah[mf], st + aoff[mf] + kb);
                ldmx4(al[mf], st + 10240 + aoff[mf] + kb);
            }
            // gate matrix
#pragma unroll
            for (int nf2 = 0; nf2 < 2; nf2++) {
                ldmx4(bh[nf2], st + 20480 + boff[nf2] + kb);
                ldmx4(bl[nf2], st + 30720 + boff[nf2] + kb);
            }
#pragma unroll
            for (int mf = 0; mf < 2; mf++)
#pragma unroll
            for (int nf2 = 0; nf2 < 2; nf2++)
#pragma unroll
            for (int j = 0; j < 2; j++) {
                int nf = nf2 * 2 + j;
                mma16816(cg[mf][nf], ah[mf], &bh[nf2][2 * j]);
                mma16816(cg[mf][nf], al[mf], &bh[nf2][2 * j]);
                mma16816(cg[mf][nf], ah[mf], &bl[nf2][2 * j]);
            }
            // up matrix
#pragma unroll
            for (int nf2 = 0; nf2 < 2; nf2++) {
                ldmx4(bh[nf2], st + 40960 + boff[nf2] + kb);
                ldmx4(bl[nf2], st + 51200 + boff[nf2] + kb);
            }
#pragma unroll
            for (int mf = 0; mf < 2; mf++)
#pragma unroll
            for (int nf2 = 0; nf2 < 2; nf2++)
#pragma unroll
            for (int j = 0; j < 2; j++) {
                int nf = nf2 * 2 + j;
                mma16816(cu[mf][nf], ah[mf], &bh[nf2][2 * j]);
                mma16816(cu[mf][nf], al[mf], &bh[nf2][2 * j]);
                mma16816(cu[mf][nf], ah[mf], &bl[nf2][2 * j]);
            }
        }
        __syncthreads();
    }

#pragma unroll
    for (int mf = 0; mf < 2; mf++)
#pragma unroll
    for (int nf = 0; nf < 4; nf++) {
        int r = m0 + wm + mf * 16 + (lane >> 2);
        int c = n0 + wn + nf * 8 + (lane & 3) * 2;
#pragma unroll
        for (int h = 0; h < 2; h++) {
            int rr = r + h * 8;
            if (rr < M) {
                float gv0 = cg[mf][nf][2 * h],     gv1 = cg[mf][nf][2 * h + 1];
                float uv0 = cu[mf][nf][2 * h],     uv1 = cu[mf][nf][2 * h + 1];
                float h0 = gv0 / (1.f + expf(-gv0)) * uv0;
                float h1 = gv1 / (1.f + expf(-gv1)) * uv1;
                size_t o = (size_t)(base + rr) * Nn + c;
                bf16 hh0, hl0, hh1, hl1;
                split_bf(h0, hh0, hl0); split_bf(h1, hh1, hl1);
                *(__nv_bfloat162*)(g_h_hi + o) = __halves2bfloat162(hh0, hh1);
                *(__nv_bfloat162*)(g_h_lo + o) = __halves2bfloat162(hl0, hl1);
            }
        }
    }
}

// ---------------------------------------------------------------------------
// Down projection GEMM. BM=128 BN=128 BK=32, 512 threads.
// Stage: Ahi 0, Alo 10240, Bhi 20480, Blo 30720; stage stride 40960.
// ---------------------------------------------------------------------------
#define STG_DN 40960
template<bool ROUTED>
__global__ void __launch_bounds__(512)
down_mma(float* __restrict__ out, int Kk) {
    int e    = ROUTED ? blockIdx.z : 0;
    int M    = ROUTED ? g_counts[e] : N_;
    int base = ROUTED ? g_offsets[e] : 0;
    int m0 = blockIdx.x * 128;
    if (m0 >= M) return;
    int n0 = blockIdx.y * 128;

    size_t eoff = ROUTED ? (size_t)e * D_ * H_ : 0;
    const bf16* Bh = (ROUTED ? g_wd_hi : g_sd_hi) + eoff;
    const bf16* Bl = (ROUTED ? g_wd_lo : g_sd_lo) + eoff;

    extern __shared__ char smem[];
    int tid = threadIdx.x;
    int row = tid >> 2;
    int kq  = (tid & 3) * 16;
    int ra = m0 + row; if (ra > M - 1) ra = M - 1;
    const char* pAh = (const char*)(g_h_hi + (size_t)(base + ra) * Kk) + kq;
    const char* pAl = (const char*)(g_h_lo + (size_t)(base + ra) * Kk) + kq;
    const char* pBh = (const char*)(Bh + (size_t)(n0 + row) * Kk) + kq;
    const char* pBl = (const char*)(Bl + (size_t)(n0 + row) * Kk) + kq;

    uint32_t sb = (uint32_t)__cvta_generic_to_shared(smem);
    uint32_t dr = sb + row * 80 + kq;

    auto issue = [&](int stage, int kt) {
        uint32_t so = stage * STG_DN;
        size_t ko = (size_t)kt * 64;
        cpa(dr + so,         pAh + ko);
        cpa(dr + so + 10240, pAl + ko);
        cpa(dr + so + 20480, pBh + ko);
        cpa(dr + so + 30720, pBl + ko);
        asm volatile("cp.async.commit_group;");
    };

    int lane = tid & 31, wid = tid >> 5;
    int wm = (wid & 3) * 32;
    int wn = (wid >> 2) * 32;
    int grp = lane >> 3, lr = lane & 7;
    uint32_t aoff[2], boff[2];
#pragma unroll
    for (int mf = 0; mf < 2; mf++)
        aoff[mf] = (uint32_t)((wm + mf * 16 + (grp & 1) * 8 + lr) * 80 + (grp >> 1) * 16);
#pragma unroll
    for (int nf2 = 0; nf2 < 2; nf2++)
        boff[nf2] = (uint32_t)((wn + nf2 * 16 + (grp >> 1) * 8 + lr) * 80 + (grp & 1) * 16);

    float cd[2][4][4];
#pragma unroll
    for (int a = 0; a < 2; a++)
#pragma unroll
    for (int b = 0; b < 4; b++)
#pragma unroll
    for (int c = 0; c < 4; c++) cd[a][b][c] = 0.f;

    const int KI = Kk / 32;
    issue(0, 0);
    for (int kt = 0; kt < KI; kt++) {
        int cur = kt & 1;
        if (kt + 1 < KI) {
            issue(cur ^ 1, kt + 1);
            asm volatile("cp.async.wait_group 1;");
        } else {
            asm volatile("cp.async.wait_group 0;");
        }
        __syncthreads();
        uint32_t st = sb + cur * STG_DN;
#pragma unroll
        for (int ks = 0; ks < 2; ks++) {
            uint32_t kb = ks * 32;
            uint32_t ah[2][4], al[2][4], bh[2][4], bl[2][4];
#pragma unroll
            for (int mf = 0; mf < 2; mf++) {
                ldmx4(ah[mf], st + aoff[mf] + kb);
                ldmx4(al[mf], st + 10240 + aoff[mf] + kb);
            }
#pragma unroll
            for (int nf2 = 0; nf2 < 2; nf2++) {
                ldmx4(bh[nf2], st + 20480 + boff[nf2] + kb);
                ldmx4(bl[nf2], st + 30720 + boff[nf2] + kb);
            }
#pragma unroll
            for (int mf = 0; mf < 2; mf++)
#pragma unroll
            for (int nf2 = 0; nf2 < 2; nf2++)
#pragma unroll
            for (int j = 0; j < 2; j++) {
                int nf = nf2 * 2 + j;
                mma16816(cd[mf][nf], ah[mf], &bh[nf2][2 * j]);
                mma16816(cd[mf][nf], al[mf], &bh[nf2][2 * j]);
                mma16816(cd[mf][nf], ah[mf], &bl[nf2][2 * j]);
            }
        }
        __syncthreads();
    }

#pragma unroll
    for (int mf = 0; mf < 2; mf++)
#pragma unroll
    for (int nf = 0; nf < 4; nf++) {
        int r = m0 + wm + mf * 16 + (lane >> 2);
        int c = n0 + wn + nf * 8 + (lane & 3) * 2;
#pragma unroll
        for (int h = 0; h < 2; h++) {
            int rr = r + h * 8;
            if (rr < M) {
                float v0 = cd[mf][nf][2 * h], v1 = cd[mf][nf][2 * h + 1];
                if (ROUTED) {
                    int p = base + rr;
                    float gt = g_pgate[p];
                    float* op = out + (size_t)g_perm[p] * D_ + c;
                    atomicAdd(op,     v0 * gt);
                    atomicAdd(op + 1, v1 * gt);
                } else {
                    *(float2*)(out + (size_t)rr * D_ + c) = make_float2(v0, v1);
                }
            }
        }
    }
}

// ---------------------------------------------------------------------------
extern "C" void kernel_launch(void* const* d_in, const int* in_sizes, int n_in,
                              void* d_out, int out_size) {
    const float* x  = (const float*)d_in[0];
    const float* rw = (const float*)d_in[1];
    const float* wg = (const float*)d_in[2];
    const float* wu = (const float*)d_in[3];
    const float* wd = (const float*)d_in[4];
    const float* sg = (const float*)d_in[5];
    const float* su = (const float*)d_in[6];
    const float* sd = (const float*)d_in[7];
    float* out = (float*)d_out;

    const int SMEM_GU = 2 * STG_GU;   // 122880
    const int SMEM_DN = 2 * STG_DN;   // 81920
    cudaFuncSetAttribute(gateup_mma<false>, cudaFuncAttributeMaxDynamicSharedMemorySize, SMEM_GU);
    cudaFuncSetAttribute(gateup_mma<true>,  cudaFuncAttributeMaxDynamicSharedMemorySize, SMEM_GU);
    cudaFuncSetAttribute(down_mma<false>,   cudaFuncAttributeMaxDynamicSharedMemorySize, SMEM_DN);
    cudaFuncSetAttribute(down_mma<true>,    cudaFuncAttributeMaxDynamicSharedMemorySize, SMEM_DN);

    bf16 *wg_hi, *wg_lo, *wu_hi, *wu_lo, *wd_hi, *wd_lo;
    bf16 *sg_hi, *sg_lo, *su_hi, *su_lo, *sd_hi, *sd_lo;
    cudaGetSymbolAddress((void**)&wg_hi, g_wg_hi); cudaGetSymbolAddress((void**)&wg_lo, g_wg_lo);
    cudaGetSymbolAddress((void**)&wu_hi, g_wu_hi); cudaGetSymbolAddress((void**)&wu_lo, g_wu_lo);
    cudaGetSymbolAddress((void**)&wd_hi, g_wd_hi); cudaGetSymbolAddress((void**)&wd_lo, g_wd_lo);
    cudaGetSymbolAddress((void**)&sg_hi, g_sg_hi); cudaGetSymbolAddress((void**)&sg_lo, g_sg_lo);
    cudaGetSymbolAddress((void**)&su_hi, g_su_hi); cudaGetSymbolAddress((void**)&su_lo, g_su_lo);
    cudaGetSymbolAddress((void**)&sd_hi, g_sd_hi); cudaGetSymbolAddress((void**)&sd_lo, g_sd_lo);

    dim3 tb(32, 8);
    tconv<<<dim3(H_ / 32, D_ / 32, E_), tb>>>(wg, wg_hi, wg_lo, D_, H_);
    tconv<<<dim3(H_ / 32, D_ / 32, E_), tb>>>(wu, wu_hi, wu_lo, D_, H_);
    tconv<<<dim3(D_ / 32, H_ / 32, E_), tb>>>(wd, wd_hi, wd_lo, H_, D_);
    tconv<<<dim3(HS_ / 32, D_ / 32, 1), tb>>>(sg, sg_hi, sg_lo, D_, HS_);
    tconv<<<dim3(HS_ / 32, D_ / 32, 1), tb>>>(su, su_hi, su_lo, D_, HS_);
    tconv<<<dim3(D_ / 32, HS_ / 32, 1), tb>>>(sd, sd_hi, sd_lo, HS_, D_);
    xconv<<<(N_ * D_ / 4) / 256, 256>>>(x);

    router_kernel<<<N_ / 8, 256>>>(x, rw);
    build_lists_kernel<<<1, 256>>>();

    // Shared expert first: its down pass initializes every out element.
    gateup_mma<false><<<dim3(N_ / 128, HS_ / 128, 1), 512, SMEM_GU>>>(HS_);
    down_mma<false><<<dim3(N_ / 128, D_ / 128, 1), 512, SMEM_DN>>>(out, HS_);

    // Routed experts: gathered grouped GEMMs + atomic scatter-add.
    gateup_mma<true><<<dim3(N_ / 128, H_ / 128, E_), 512, SMEM_GU>>>(H_);
    down_mma<true><<<dim3(N_ / 128, D_ / 128, E_), 512, SMEM_DN>>>(out, H_);
}